// round 12
// baseline (speedup 1.0000x reference)
#include <cuda_runtime.h>
#include <cuda_bf16.h>
#include <math.h>
#include <stdint.h>

// Problem constants
#define BB   4
#define DIN  1024
#define CHN  512
#define HH   50
#define WW   76
#define SP   3800          // HH*WW
#define AN   9             // anchors per position
#define KTOT 34200         // SP*AN
#define NPAD 65536
#define CHUNK 8192         // sort chunk (must be >= PRE_NMS)
#define PRE_NMS  6000
#define POST_NMS 300
#define NMS_THRESH 0.7f
#define MIN_SIZE   16.0f
#define STRIDE_F   16.0f

#define NSTAGE_HEAD 16     // 512/32

// HMMA conv geometry: CTA tile 128 oc x 64 sp, KTILE=32 per stage, 512 threads.
#define NST     288                 // 9 taps * (1024/32)
#define AFRAG_B 8192                // per-split A tile: 8 oct*2 kstep*32 lane*16B
#define ATILE3  24576               // 3 splits
#define BROWB   80                  // B row stride bytes (40 bf16)
#define BSPLITB 5120                // 64 rows * 80B
#define BTILE3  15360
#define SMEM_B_OFF 49152            // 2 * ATILE3
#define SMEM_CONV_TOTAL (SMEM_B_OFF + 2 * BTILE3)   // 79872

typedef unsigned long long ull;

// ---------------- scratch (device globals; no allocation allowed) -------------
__device__ uint32_t g_wfrag[(size_t)4 * NST * 3 * 2048];  // A fragments, 28MB
__device__ float g_wpad[DIN * 64];                    // heads weights [c][o]
__device__ float g_x [BB * CHN * SP];                 // relu(conv) output
__device__ float g_cls[BB * 18 * SP];
__device__ float g_bbox[BB * 36 * SP];
__device__ ull   g_keys[BB * NPAD];
__device__ float g_boxes[BB * KTOT * 4];
__device__ float g_tb[BB * PRE_NMS * 4];
__device__ float g_ts[BB * PRE_NMS];
__device__ int   g_keep[BB * POST_NMS];

__constant__ float c_ab[9][4] = {
    { -84.f,  -40.f,  99.f,  55.f},
    {-176.f,  -88.f, 191.f, 103.f},
    {-360.f, -184.f, 375.f, 199.f},
    { -56.f,  -56.f,  71.f,  71.f},
    {-120.f, -120.f, 135.f, 135.f},
    {-248.f, -248.f, 263.f, 263.f},
    { -36.f,  -80.f,  51.f,  95.f},
    { -80.f, -168.f,  95.f, 183.f},
    {-168.f, -344.f, 183.f, 359.f},
};

// scalar exact twoSum fold: (hi, lo) += v
#define TWOSUM_FOLD(hi, lo, v)                                          \
    {                                                                    \
        const float _s = __fadd_rn((hi), (v));                           \
        const float _z = __fsub_rn(_s, (hi));                            \
        const float _e = __fadd_rn(__fsub_rn((hi), __fsub_rn(_s, _z)),   \
                                   __fsub_rn((v), _z));                  \
        (hi) = _s;                                                       \
        (lo) = __fadd_rn((lo), _e);                                      \
    }

static __device__ __forceinline__ unsigned short bfbits(__nv_bfloat16 h) {
    return *reinterpret_cast<unsigned short*>(&h);
}

// split fp32 into 3 bf16 bit patterns
static __device__ __forceinline__ void split3(float v, unsigned short& u1,
                                              unsigned short& u2, unsigned short& u3) {
    const __nv_bfloat16 s1 = __float2bfloat16(v);
    const float r1 = __fsub_rn(v, __bfloat162float(s1));
    const __nv_bfloat16 s2 = __float2bfloat16(r1);
    const float r2 = __fsub_rn(r1, __bfloat162float(s2));
    const __nv_bfloat16 s3 = __float2bfloat16(r2);
    u1 = bfbits(s1); u2 = bfbits(s2); u3 = bfbits(s3);
}

// mma.sync m16n8k16 bf16 -> fp32, C += A*B
static __device__ __forceinline__ void mma16816(float* c, const uint32_t* a,
                                                const uint32_t* b) {
    asm volatile(
        "mma.sync.aligned.m16n8k16.row.col.f32.bf16.bf16.f32 "
        "{%0,%1,%2,%3}, {%4,%5,%6,%7}, {%8,%9}, {%0,%1,%2,%3};"
        : "+f"(c[0]), "+f"(c[1]), "+f"(c[2]), "+f"(c[3])
        : "r"(a[0]), "r"(a[1]), "r"(a[2]), "r"(a[3]), "r"(b[0]), "r"(b[1]));
}

static __device__ __forceinline__ uint32_t smem_u32(const void* p) {
    uint32_t a;
    asm("{ .reg .u64 t; cvta.to.shared.u64 t, %1; cvt.u32.u64 %0, t; }" : "=r"(a) : "l"(p));
    return a;
}

// ---------------- 0a: weight split into per-lane fragment layout --------------
__global__ void k_prep_wfrag(const float* __restrict__ w) {
    const int i = blockIdx.x * blockDim.x + threadIdx.x;
    const int NTOT = 4 * NST * 8 * 2 * 32;
    if (i >= NTOT) return;
    const int lane  = i & 31;
    const int kstep = (i >> 5) & 1;
    const int oct   = (i >> 6) & 7;
    const int st    = (i >> 9) % NST;
    const int ot    = i / (NST << 9);
    const int tap = st >> 5;
    const int icb = (st & 31) << 5;

    uint32_t regs[3][4];
#pragma unroll
    for (int s = 0; s < 3; s++)
#pragma unroll
        for (int r = 0; r < 4; r++) regs[s][r] = 0u;

#pragma unroll
    for (int r = 0; r < 4; r++) {
#pragma unroll
        for (int h = 0; h < 2; h++) {
            const int m  = (lane >> 2) + 8 * (r & 1);
            const int kk = 2 * (lane & 3) + h + 8 * (r >> 1);
            const int oc = ot * 128 + oct * 16 + m;
            const int ic = icb + kstep * 16 + kk;
            const float v = w[((size_t)oc * DIN + ic) * 9 + tap];
            unsigned short u1, u2, u3;
            split3(v, u1, u2, u3);
            regs[0][r] |= (uint32_t)u1 << (16 * h);
            regs[1][r] |= (uint32_t)u2 << (16 * h);
            regs[2][r] |= (uint32_t)u3 << (16 * h);
        }
    }
    const int fidx = (oct * 2 + kstep) * 32 + lane;   // 0..511
#pragma unroll
    for (int s = 0; s < 3; s++) {
        const size_t b32 = (((size_t)(ot * NST + st) * 3 + s) * 2048) + (size_t)fidx * 4;
        reinterpret_cast<uint4*>(g_wfrag)[b32 >> 2] =
            make_uint4(regs[s][0], regs[s][1], regs[s][2], regs[s][3]);
    }
}

// ---------------- 0b: pack heads weights [c][o] -------------------------------
__global__ void k_prep_headw(const float* __restrict__ cls_w,
                             const float* __restrict__ bbox_w) {
    int i = blockIdx.x * blockDim.x + threadIdx.x;
    if (i >= DIN * 64) return;
    const int o = i & 63;
    const int c = i >> 6;
    float v = 0.f;
    if (c < CHN) {
        if (o < 18)      v = cls_w[(size_t)o * CHN + c];
        else if (o < 54) v = bbox_w[(size_t)(o - 18) * CHN + c];
    }
    g_wpad[i] = v;
}

// ---------------- 1: 3x3 conv via mma.sync bf16 triple-split ------------------
// 512 threads, 16 warps: warp = (oc-group of 16) x (sp-half of 32).
// A tiles via cp.async (no register staging); B split on the fly.
// Double-buffered stages (KTILE=32); fold into hi/lo every 2 stages (K=64).
__global__ __launch_bounds__(512, 1) void k_conv_mma(
    const float* __restrict__ in, const float* __restrict__ bias) {
    extern __shared__ char smem[];
    const uint32_t smem_base = smem_u32(smem);
    const int tid  = threadIdx.x;
    const int wrp  = tid >> 5;
    const int lane = tid & 31;

    const int ot  = blockIdx.y;
    const int b   = blockIdx.z;
    const int sp0 = blockIdx.x * 64;

    const float* inb = in + (size_t)b * DIN * SP;
    const char*  wbase = reinterpret_cast<const char*>(g_wfrag);

    // B producer mapping: 512 threads cover 64 sp x 8 k-quads of 4
    const int bsp = tid & 63;
    const int kq  = tid >> 6;          // 0..7, 4 k each
    const int pos = sp0 + bsp;
    const bool okp = (pos < SP);
    const int ph = pos / WW;
    const int pw = pos - ph * WW;

    float acc[4][4], hi[4][4], lo[4][4];
#pragma unroll
    for (int t2 = 0; t2 < 4; t2++)
#pragma unroll
        for (int r = 0; r < 4; r++) { hi[t2][r] = 0.f; lo[t2][r] = 0.f; }

    float rb[4];

    // issue cp.async for A tile of stage s_ into buffer buf_
#define CONV_A_ASYNC(s_, buf_)                                                 \
    {                                                                          \
        const char* gsrc_ = wbase + ((size_t)(ot * NST + (s_))) * ATILE3;      \
        const uint32_t sdst_ = smem_base + (buf_) * ATILE3;                    \
        _Pragma("unroll")                                                      \
        for (int u = 0; u < 3; u++) {                                          \
            const int off_ = (u * 512 + tid) * 16;                             \
            asm volatile("cp.async.cg.shared.global [%0], [%1], 16;"           \
                :: "r"(sdst_ + off_), "l"(gsrc_ + off_));                      \
        }                                                                      \
        asm volatile("cp.async.commit_group;");                                \
    }

    // prefetch B values of stage s_ into rb
#define CONV_B_PREFETCH(s_)                                                    \
    {                                                                          \
        const int st_ = (s_);                                                  \
        const int tap_ = st_ >> 5;                                             \
        const int ic0_ = (st_ & 31) << 5;                                      \
        const int dy_ = tap_ / 3 - 1, dx_ = tap_ % 3 - 1;                      \
        const int hh_ = ph + dy_, w2_ = pw + dx_;                              \
        const bool ok_ = okp && (hh_ >= 0) && (hh_ < HH) &&                    \
                         (w2_ >= 0) && (w2_ < WW);                             \
        const int ipp_ = hh_ * WW + w2_;                                       \
        _Pragma("unroll")                                                      \
        for (int j = 0; j < 4; j++)                                            \
            rb[j] = ok_ ? __ldg(inb + (size_t)(ic0_ + kq * 4 + j) * SP + ipp_) \
                        : 0.f;                                                 \
    }

    CONV_A_ASYNC(0, 0);
    CONV_B_PREFETCH(0);

    const int oct    = wrp & 7;
    const int spbase = (wrp >> 3) * 32;

    for (int s = 0; s < NST; s++) {
        const int buf = s & 1;
        // ---- store B: split + pair-XOR layout (2 pairs per thread)
        {
            char* bbase = smem + SMEM_B_OFF + buf * BTILE3;
#pragma unroll
            for (int j = 0; j < 4; j += 2) {
                const int k  = kq * 4 + j;
                const int pi = k >> 1;
                const int pos2 = (pi & ~3) | ((pi & 3) ^ (bsp & 3));
                unsigned short a1, a2, a3, b1, b2, b3;
                split3(rb[j],     a1, a2, a3);
                split3(rb[j + 1], b1, b2, b3);
                char* p = bbase + bsp * BROWB + pos2 * 4;
                *reinterpret_cast<uint32_t*>(p) =
                    (uint32_t)a1 | ((uint32_t)b1 << 16);
                *reinterpret_cast<uint32_t*>(p + BSPLITB) =
                    (uint32_t)a2 | ((uint32_t)b2 << 16);
                *reinterpret_cast<uint32_t*>(p + 2 * BSPLITB) =
                    (uint32_t)a3 | ((uint32_t)b3 << 16);
            }
        }
        // A(s) must have landed before the barrier makes it visible to all
        asm volatile("cp.async.wait_group 0;" ::: "memory");
        __syncthreads();
        if (s + 1 < NST) {
            CONV_A_ASYNC(s + 1, buf ^ 1);
            CONV_B_PREFETCH(s + 1);
        }

        // ---- compute
        const char* abase = smem + buf * ATILE3;
        const char* bbse  = smem + SMEM_B_OFF + buf * BTILE3;
        if ((s & 1) == 0) {
#pragma unroll
            for (int t2 = 0; t2 < 4; t2++)
#pragma unroll
                for (int r = 0; r < 4; r++) acc[t2][r] = 0.f;
        }
#pragma unroll
        for (int kstep = 0; kstep < 2; kstep++) {
            uint32_t af[3][4];
#pragma unroll
            for (int sa = 0; sa < 3; sa++) {
                const uint4 v = *reinterpret_cast<const uint4*>(
                    abase + sa * AFRAG_B + ((oct * 2 + kstep) * 32 + lane) * 16);
                af[sa][0] = v.x; af[sa][1] = v.y; af[sa][2] = v.z; af[sa][3] = v.w;
            }
#pragma unroll
            for (int spt = 0; spt < 4; spt++) {
                const int spl = spbase + spt * 8 + (lane >> 2);
                const int pbase = kstep * 8 + ((lane & 3) ^ ((lane >> 2) & 3));
                uint32_t bf[3][2];
#pragma unroll
                for (int sb = 0; sb < 3; sb++) {
                    const char* p = bbse + sb * BSPLITB + spl * BROWB + pbase * 4;
                    bf[sb][0] = *reinterpret_cast<const uint32_t*>(p);
                    bf[sb][1] = *reinterpret_cast<const uint32_t*>(p + 16);
                }
                float* C = acc[spt];
                mma16816(C, af[0], bf[0]);   // s1*s1
                mma16816(C, af[0], bf[1]);   // s1*s2
                mma16816(C, af[1], bf[0]);   // s2*s1
                mma16816(C, af[1], bf[1]);   // s2*s2
                mma16816(C, af[0], bf[2]);   // s1*s3
                mma16816(C, af[2], bf[0]);   // s3*s1
            }
        }
        if (s & 1) {
#pragma unroll
            for (int t2 = 0; t2 < 4; t2++)
#pragma unroll
                for (int r = 0; r < 4; r++) {
                    TWOSUM_FOLD(hi[t2][r], lo[t2][r], acc[t2][r]);
                }
        }
    }
#undef CONV_A_ASYNC
#undef CONV_B_PREFETCH

    // ---- epilogue: collapse, bias + relu (ref op order), write g_x
    // C frag: r=0,1 -> row lane>>2, col 2(lane&3)+{0,1}; r=2,3 -> row+8.
#pragma unroll
    for (int spt = 0; spt < 4; spt++) {
#pragma unroll
        for (int r = 0; r < 4; r++) {
            const int oc  = ot * 128 + oct * 16 + (lane >> 2) + 8 * (r >> 1);
            const int spx = sp0 + spbase + spt * 8 + 2 * (lane & 3) + (r & 1);
            if (spx < SP) {
                const float cf = __fadd_rn(hi[spt][r], lo[spt][r]);
                const float v  = __fadd_rn(cf, bias[oc]);
                g_x[((size_t)b * CHN + oc) * SP + spx] = v > 0.f ? v : 0.f;
            }
        }
    }
}

// ---------------- 2: 1x1 heads as 64x64-tile GEMM -----------------------------
#define ZERO44(c)                                       \
    {                                                   \
        _Pragma("unroll")                               \
        for (int _i = 0; _i < 4; _i++)                  \
            _Pragma("unroll")                           \
            for (int _j = 0; _j < 4; _j++) c[_i][_j] = 0.f; \
    }
#define ADD44(a, c)                                     \
    {                                                   \
        _Pragma("unroll")                               \
        for (int _i = 0; _i < 4; _i++)                  \
            _Pragma("unroll")                           \
            for (int _j = 0; _j < 4; _j++)              \
                a[_i][_j] = __fadd_rn(a[_i][_j], c[_i][_j]); \
    }
#define ACC8(c, As, Bs, kb_)                                                   \
    {                                                                          \
        _Pragma("unroll")                                                      \
        for (int kk2 = 0; kk2 < 8; kk2++) {                                    \
            const int kk = (kb_) + kk2;                                        \
            const float4 av = *reinterpret_cast<const float4*>(&(As)[kk][ty*4]);\
            const float4 bv = *reinterpret_cast<const float4*>(&(Bs)[kk][tx*4]);\
            c[0][0] = fmaf(av.x, bv.x, c[0][0]); c[0][1] = fmaf(av.x, bv.y, c[0][1]); \
            c[0][2] = fmaf(av.x, bv.z, c[0][2]); c[0][3] = fmaf(av.x, bv.w, c[0][3]); \
            c[1][0] = fmaf(av.y, bv.x, c[1][0]); c[1][1] = fmaf(av.y, bv.y, c[1][1]); \
            c[1][2] = fmaf(av.y, bv.z, c[1][2]); c[1][3] = fmaf(av.y, bv.w, c[1][3]); \
            c[2][0] = fmaf(av.z, bv.x, c[2][0]); c[2][1] = fmaf(av.z, bv.y, c[2][1]); \
            c[2][2] = fmaf(av.z, bv.z, c[2][2]); c[2][3] = fmaf(av.z, bv.w, c[2][3]); \
            c[3][0] = fmaf(av.w, bv.x, c[3][0]); c[3][1] = fmaf(av.w, bv.y, c[3][1]); \
            c[3][2] = fmaf(av.w, bv.z, c[3][2]); c[3][3] = fmaf(av.w, bv.w, c[3][3]); \
        }                                                                      \
    }

__global__ __launch_bounds__(256, 2) void k_heads_gemm(
    const float* __restrict__ cls_b, const float* __restrict__ bbox_b) {
    const int b   = blockIdx.z;
    const int sp0 = blockIdx.x * 64;
    const int t   = threadIdx.x;
    const int tx  = t & 15;
    const int ty  = t >> 4;

    __shared__ float a_s[2][32][64];
    __shared__ float b_s[2][32][64];

    float hi[4][4], lo[4][4], cA[4][4];
#pragma unroll
    for (int i = 0; i < 4; i++)
#pragma unroll
        for (int j = 0; j < 4; j++) { hi[i][j] = 0.f; lo[i][j] = 0.f; }

    const float* xb = g_x + (size_t)b * CHN * SP;

    const int ss  = t & 63;
    const int pos = sp0 + ss;
    const bool okp = (pos < SP);
    const int kb  = t >> 6;

    const int a_kk = t >> 4;
    const int a_oo = (t & 15) * 4;

    float4 ra0, ra1;
    float rb[8];

#define HEAD_PREFETCH(s_)                                                      \
    {                                                                          \
        const int ic0_ = (s_) << 5;                                            \
        const float* wt_ = g_wpad + (size_t)(ic0_ + a_kk) * 64 + a_oo;         \
        ra0 = *reinterpret_cast<const float4*>(wt_);                           \
        ra1 = *reinterpret_cast<const float4*>(wt_ + 16 * 64);                 \
        _Pragma("unroll")                                                      \
        for (int u = 0; u < 8; u++) {                                          \
            rb[u] = okp ? xb[(size_t)(ic0_ + kb + u * 4) * SP + pos] : 0.f;    \
        }                                                                      \
    }

    HEAD_PREFETCH(0);

    for (int s = 0; s < NSTAGE_HEAD; s++) {
        const int buf = s & 1;
        *reinterpret_cast<float4*>(&a_s[buf][a_kk][a_oo])      = ra0;
        *reinterpret_cast<float4*>(&a_s[buf][a_kk + 16][a_oo]) = ra1;
#pragma unroll
        for (int u = 0; u < 8; u++) b_s[buf][kb + u * 4][ss] = rb[u];
        __syncthreads();
        if (s + 1 < NSTAGE_HEAD) HEAD_PREFETCH(s + 1);
        float cB[4][4];
        if ((s & 1) == 0) {
            ZERO44(cA);
            ACC8(cA, a_s[buf], b_s[buf], 0);
        } else {
            ZERO44(cB);
            ACC8(cB, a_s[buf], b_s[buf], 0);
            ADD44(cA, cB);
        }
#pragma unroll
        for (int u = 1; u < 4; u++) {
            ZERO44(cB);
            ACC8(cB, a_s[buf], b_s[buf], 8 * u);
            ADD44(cA, cB);
        }
        if (s & 1) {
#pragma unroll
            for (int i = 0; i < 4; i++)
#pragma unroll
                for (int j = 0; j < 4; j++) {
                    TWOSUM_FOLD(hi[i][j], lo[i][j], cA[i][j]);
                }
        }
    }
#undef HEAD_PREFETCH

#pragma unroll
    for (int i = 0; i < 4; i++) {
        const int o = ty * 4 + i;
        if (o >= 54) continue;
        const float bv = (o < 18) ? cls_b[o] : bbox_b[o - 18];
        float* outp = (o < 18)
            ? (g_cls  + ((size_t)b * 18 + o)        * SP)
            : (g_bbox + ((size_t)b * 36 + (o - 18)) * SP);
#pragma unroll
        for (int j = 0; j < 4; j++) {
            const int p = sp0 + tx * 4 + j;
            if (p < SP) {
                const float cf = __fadd_rn(hi[i][j], lo[i][j]);
                outp[p] = __fadd_rn(cf, bv);
            }
        }
    }
}

// ---------------- 3: decode + clip + filter + key build ----------------------
__device__ __forceinline__ unsigned int fmono(float f) {
    unsigned int u = __float_as_uint(f);
    return (u & 0x80000000u) ? ~u : (u | 0x80000000u);
}
__device__ __forceinline__ float fmono_inv(unsigned int u) {
    unsigned int v = (u & 0x80000000u) ? (u & 0x7FFFFFFFu) : ~u;
    return __uint_as_float(v);
}

__global__ void k_decode(const float* __restrict__ im_info) {
    const int i = blockIdx.x * blockDim.x + threadIdx.x;
    const int b = blockIdx.y;
    if (i >= NPAD) return;
    if (i >= KTOT) { g_keys[(size_t)b * NPAD + i] = 0ull; return; }

    const int pos = i / AN;
    const int a   = i - pos * AN;
    const int h   = pos / WW;
    const int w   = pos - h * WW;

    const float c0 = g_cls[((size_t)b * 18 + a) * SP + pos];
    const float c1 = g_cls[((size_t)b * 18 + 9 + a) * SP + pos];
    const float m  = fmaxf(c0, c1);
    const float e0 = expf(__fsub_rn(c0, m));
    const float e1 = expf(__fsub_rn(c1, m));
    const float fg = e1 / __fadd_rn(e0, e1);

    const float d0 = g_bbox[((size_t)b * 36 + a * 4 + 0) * SP + pos];
    const float d1 = g_bbox[((size_t)b * 36 + a * 4 + 1) * SP + pos];
    const float d2 = g_bbox[((size_t)b * 36 + a * 4 + 2) * SP + pos];
    const float d3 = g_bbox[((size_t)b * 36 + a * 4 + 3) * SP + pos];

    const float sx = w * STRIDE_F, sy = h * STRIDE_F;
    const float ax1 = __fadd_rn(c_ab[a][0], sx), ay1 = __fadd_rn(c_ab[a][1], sy);
    const float ax2 = __fadd_rn(c_ab[a][2], sx), ay2 = __fadd_rn(c_ab[a][3], sy);
    const float aw  = __fadd_rn(__fsub_rn(ax2, ax1), 1.f);
    const float ah  = __fadd_rn(__fsub_rn(ay2, ay1), 1.f);
    const float axc = __fadd_rn(ax1, __fmul_rn(0.5f, aw));
    const float ayc = __fadd_rn(ay1, __fmul_rn(0.5f, ah));

    const float cx  = __fadd_rn(axc, __fmul_rn(d0, aw));
    const float cy  = __fadd_rn(ayc, __fmul_rn(d1, ah));
    const float pw  = __fmul_rn(expf(d2), aw);
    const float phh = __fmul_rn(expf(d3), ah);

    float x1 = __fsub_rn(cx, __fmul_rn(0.5f, pw));
    float y1 = __fsub_rn(cy, __fmul_rn(0.5f, phh));
    float x2 = __fadd_rn(cx, __fmul_rn(0.5f, pw));
    float y2 = __fadd_rn(cy, __fmul_rn(0.5f, phh));

    const float i0 = im_info[b * 3 + 0];
    const float i1 = im_info[b * 3 + 1];
    const float i2 = im_info[b * 3 + 2];
    x1 = fminf(fmaxf(x1, 0.f), __fsub_rn(i1, 1.f));
    x2 = fminf(fmaxf(x2, 0.f), __fsub_rn(i1, 1.f));
    y1 = fminf(fmaxf(y1, 0.f), __fsub_rn(i0, 1.f));
    y2 = fminf(fmaxf(y2, 0.f), __fsub_rn(i0, 1.f));

    const float ws = __fadd_rn(__fsub_rn(x2, x1), 1.f);
    const float hs = __fadd_rn(__fsub_rn(y2, y1), 1.f);
    const float ms = __fmul_rn(MIN_SIZE, i2);
    const float score = (ws >= ms && hs >= ms) ? fg : -INFINITY;

    float* bo = g_boxes + ((size_t)b * KTOT + i) * 4;
    bo[0] = x1; bo[1] = y1; bo[2] = x2; bo[3] = y2;

    g_keys[(size_t)b * NPAD + i] =
        ((ull)fmono(score) << 32) | (ull)(0xFFFFFFFFu - (unsigned)i);
}

// ---------------- 4a: sort 8192-chunks descending in smem ---------------------
__global__ __launch_bounds__(1024) void k_sort_chunk() {
    extern __shared__ ull sh[];
    const int b = blockIdx.y;
    ull* g = g_keys + (size_t)b * NPAD + (size_t)blockIdx.x * CHUNK;
    for (int i = threadIdx.x; i < CHUNK; i += 1024) sh[i] = g[i];
    __syncthreads();
    for (int len = 2; len <= CHUNK; len <<= 1) {
        for (int j = len >> 1; j > 0; j >>= 1) {
            for (int i = threadIdx.x; i < CHUNK; i += 1024) {
                const int ixj = i ^ j;
                if (ixj > i) {
                    const ull a = sh[i], c = sh[ixj];
                    const bool desc = ((i & len) == 0);
                    if (desc ? (a < c) : (a > c)) { sh[i] = c; sh[ixj] = a; }
                }
            }
            __syncthreads();
        }
    }
    for (int i = threadIdx.x; i < CHUNK; i += 1024) g[i] = sh[i];
}

// ---------------- 4b: merge two sorted-desc runs, keep top CHUNK --------------
__global__ __launch_bounds__(1024) void k_merge_top(int run_stride) {
    extern __shared__ ull sh[];
    const int b = blockIdx.y;
    ull* gA = g_keys + (size_t)b * NPAD + (size_t)blockIdx.x * 2 * run_stride;
    ull* gB = gA + run_stride;
    for (int i = threadIdx.x; i < CHUNK; i += 1024) {
        const ull a = gA[i];
        const ull c = gB[CHUNK - 1 - i];
        sh[i] = a > c ? a : c;
    }
    __syncthreads();
    for (int j = CHUNK >> 1; j > 0; j >>= 1) {
        for (int i = threadIdx.x; i < CHUNK; i += 1024) {
            const int ixj = i ^ j;
            if (ixj > i) {
                const ull a = sh[i], c = sh[ixj];
                if (a < c) { sh[i] = c; sh[ixj] = a; }
            }
        }
        __syncthreads();
    }
    for (int i = threadIdx.x; i < CHUNK; i += 1024) gA[i] = sh[i];
}

// ---------------- 5: gather top-k --------------------------------------------
__global__ void k_gather() {
    const int i = blockIdx.x * blockDim.x + threadIdx.x;
    const int b = blockIdx.y;
    if (i >= PRE_NMS) return;
    const ull key = g_keys[(size_t)b * NPAD + i];
    const unsigned int idx = 0xFFFFFFFFu - (unsigned int)(key & 0xFFFFFFFFull);
    g_ts[(size_t)b * PRE_NMS + i] = fmono_inv((unsigned int)(key >> 32));
    const float* src = g_boxes + ((size_t)b * KTOT + idx) * 4;
    float* dst = g_tb + ((size_t)b * PRE_NMS + i) * 4;
    dst[0] = src[0]; dst[1] = src[1]; dst[2] = src[2]; dst[3] = src[3];
}

// ---------------- 6: greedy NMS, 1 block per image ---------------------------
__global__ __launch_bounds__(1024) void k_nms() {
    const int b = blockIdx.x;
    const int tid = threadIdx.x;
    __shared__ unsigned char alive[PRE_NMS];
    __shared__ int s_head, s_cur;

    const float* ts = g_ts + (size_t)b * PRE_NMS;
    const float* tb = g_tb + (size_t)b * PRE_NMS * 4;

    for (int i = tid; i < PRE_NMS; i += blockDim.x)
        alive[i] = (ts[i] != -INFINITY) ? 1 : 0;
    if (tid == 0) s_head = 0;
    __syncthreads();

    for (int r = 0; r < POST_NMS; r++) {
        if (tid == 0) {
            int h = s_head;
            while (h < PRE_NMS && !alive[h]) h++;
            s_head = h;
            s_cur = (h < PRE_NMS) ? h : 0;
            g_keep[b * POST_NMS + r] = s_cur;
        }
        __syncthreads();
        const int j = s_cur;
        const float jx1 = tb[j * 4 + 0], jy1 = tb[j * 4 + 1];
        const float jx2 = tb[j * 4 + 2], jy2 = tb[j * 4 + 3];
        const float ja = __fmul_rn(__fadd_rn(__fsub_rn(jx2, jx1), 1.f),
                                   __fadd_rn(__fsub_rn(jy2, jy1), 1.f));
        for (int i = tid; i < PRE_NMS; i += blockDim.x) {
            if (!alive[i]) continue;
            const float x1 = tb[i * 4 + 0], y1 = tb[i * 4 + 1];
            const float x2 = tb[i * 4 + 2], y2 = tb[i * 4 + 3];
            const float xx1 = fmaxf(jx1, x1), yy1 = fmaxf(jy1, y1);
            const float xx2 = fminf(jx2, x2), yy2 = fminf(jy2, y2);
            const float iw = fmaxf(0.f, __fadd_rn(__fsub_rn(xx2, xx1), 1.f));
            const float ih = fmaxf(0.f, __fadd_rn(__fsub_rn(yy2, yy1), 1.f));
            const float inter = __fmul_rn(iw, ih);
            const float ia = __fmul_rn(__fadd_rn(__fsub_rn(x2, x1), 1.f),
                                       __fadd_rn(__fsub_rn(y2, y1), 1.f));
            const float iou = inter / __fsub_rn(__fadd_rn(ja, ia), inter);
            if (iou > NMS_THRESH) alive[i] = 0;
        }
        __syncthreads();
    }
}

// ---------------- 7: write outputs -------------------------------------------
__global__ void k_writeout(float* __restrict__ out) {
    const int t = blockIdx.x * blockDim.x + threadIdx.x;
    if (t >= BB * POST_NMS) return;
    const int b = t / POST_NMS;
    const int j = g_keep[t];
    out[t] = g_ts[(size_t)b * PRE_NMS + j];
    const float* src = g_tb + ((size_t)b * PRE_NMS + j) * 4;
    float* dst = out + BB * POST_NMS + (size_t)t * 4;
    dst[0] = src[0]; dst[1] = src[1]; dst[2] = src[2]; dst[3] = src[3];
}

// ---------------- launch ------------------------------------------------------
extern "C" void kernel_launch(void* const* d_in, const int* in_sizes, int n_in,
                              void* d_out, int out_size) {
    const float* base_feat = (const float*)d_in[0];
    const float* im_info   = (const float*)d_in[1];
    // d_in[2] gt_boxes, d_in[3] num_boxes: unused
    const float* conv_w    = (const float*)d_in[4];
    const float* conv_b    = (const float*)d_in[5];
    const float* cls_w     = (const float*)d_in[6];
    const float* cls_b     = (const float*)d_in[7];
    const float* bbox_w    = (const float*)d_in[8];
    const float* bbox_b    = (const float*)d_in[9];
    float* out = (float*)d_out;

    const int SORT_SMEM = CHUNK * (int)sizeof(ull);   // 64KB
    cudaFuncSetAttribute(k_sort_chunk, cudaFuncAttributeMaxDynamicSharedMemorySize, SORT_SMEM);
    cudaFuncSetAttribute(k_merge_top,  cudaFuncAttributeMaxDynamicSharedMemorySize, SORT_SMEM);
    cudaFuncSetAttribute(k_conv_mma,   cudaFuncAttributeMaxDynamicSharedMemorySize, SMEM_CONV_TOTAL);

    {   // weight prep: fragment-layout bf16 triple-split; heads pack
        const int n = 4 * NST * 8 * 2 * 32;
        k_prep_wfrag<<<(n + 255) / 256, 256>>>(conv_w);
        k_prep_headw<<<(DIN * 64 + 255) / 256, 256>>>(cls_w, bbox_w);
    }
    {   // conv via mma.sync bf16 (tensor pipe), 512 threads / 16 warps
        dim3 grid((SP + 63) / 64, 4, BB);
        k_conv_mma<<<grid, 512, SMEM_CONV_TOTAL>>>(base_feat, conv_b);
    }
    {   // heads GEMM
        dim3 grid((SP + 63) / 64, 1, BB);
        k_heads_gemm<<<grid, 256>>>(cls_b, bbox_b);
    }
    {   // decode
        dim3 grid((NPAD + 255) / 256, BB);
        k_decode<<<grid, 256>>>(im_info);
    }
    {   // sort: 8 chunk-sorts, then top-8192 merge tree 8 -> 4 -> 2 -> 1
        dim3 g0(NPAD / CHUNK, BB);
        k_sort_chunk<<<g0, 1024, SORT_SMEM>>>();
        dim3 g1(4, BB); k_merge_top<<<g1, 1024, SORT_SMEM>>>(CHUNK);
        dim3 g2(2, BB); k_merge_top<<<g2, 1024, SORT_SMEM>>>(2 * CHUNK);
        dim3 g3(1, BB); k_merge_top<<<g3, 1024, SORT_SMEM>>>(4 * CHUNK);
    }
    {
        dim3 grid((PRE_NMS + 255) / 256, BB);
        k_gather<<<grid, 256>>>();
    }
    k_nms<<<BB, 1024>>>();
    k_writeout<<<(BB * POST_NMS + 255) / 256, 256>>>(out);
}

// round 17
// speedup vs baseline: 1.2583x; 1.2583x over previous
#include <cuda_runtime.h>
#include <cuda_bf16.h>
#include <cuda_fp16.h>
#include <math.h>
#include <stdint.h>

// Problem constants
#define BB   4
#define DIN  1024
#define CHN  512
#define HH   50
#define WW   76
#define SP   3800          // HH*WW
#define AN   9             // anchors per position
#define KTOT 34200         // SP*AN
#define NPAD 65536
#define CHUNK 8192         // sort chunk (must be >= PRE_NMS)
#define PRE_NMS  6000
#define POST_NMS 300
#define NMS_THRESH 0.7f
#define MIN_SIZE   16.0f
#define STRIDE_F   16.0f

#define NSTAGE_HEAD 16     // 512/32

// Weight pre-scale: lifts fp16 split residual out of subnormal range.
#define WSCALE     4096.0f          // 2^12 (exact)
#define WSCALE_INV 0.000244140625f  // 2^-12 (exact)

// HMMA conv geometry: CTA tile 128 oc x 64 sp, KTILE=32 per stage, 512 threads.
// fp16 double-split on 2^12-scaled weights: 2 splits, 4 mmas per k16 step.
#define NST     288                 // 9 taps * (1024/32)
#define ASPLIT_B 8192               // per-split A tile: 8 oct*2 kstep*32 lane*16B
#define ATILE2  16384               // 2 splits
#define BROWB   80                  // B row stride bytes (40 fp16)
#define BSPLITB 5120                // 64 rows * 80B
#define BTILE2  10240               // 2 splits
#define SMEM_B_OFF 32768            // 2 * ATILE2
#define SMEM_CONV_TOTAL (SMEM_B_OFF + 2 * BTILE2)   // 53248

typedef unsigned long long ull;

// ---------------- scratch (device globals; no allocation allowed) -------------
__device__ uint32_t g_wfrag[(size_t)4 * NST * 2 * 2048];  // A fragments (fp16, 2 splits)
__device__ float g_wpad[DIN * 64];                    // heads weights [c][o]
__device__ float g_x [BB * CHN * SP];                 // relu(conv) output
__device__ float g_cls[BB * 18 * SP];
__device__ float g_bbox[BB * 36 * SP];
__device__ ull   g_keys[BB * NPAD];
__device__ float g_boxes[BB * KTOT * 4];
__device__ float g_tb[BB * PRE_NMS * 4];
__device__ float g_ts[BB * PRE_NMS];
__device__ int   g_keep[BB * POST_NMS];

__constant__ float c_ab[9][4] = {
    { -84.f,  -40.f,  99.f,  55.f},
    {-176.f,  -88.f, 191.f, 103.f},
    {-360.f, -184.f, 375.f, 199.f},
    { -56.f,  -56.f,  71.f,  71.f},
    {-120.f, -120.f, 135.f, 135.f},
    {-248.f, -248.f, 263.f, 263.f},
    { -36.f,  -80.f,  51.f,  95.f},
    { -80.f, -168.f,  95.f, 183.f},
    {-168.f, -344.f, 183.f, 359.f},
};

// scalar exact twoSum fold: (hi, lo) += v
#define TWOSUM_FOLD(hi, lo, v)                                          \
    {                                                                    \
        const float _s = __fadd_rn((hi), (v));                           \
        const float _z = __fsub_rn(_s, (hi));                            \
        const float _e = __fadd_rn(__fsub_rn((hi), __fsub_rn(_s, _z)),   \
                                   __fsub_rn((v), _z));                  \
        (hi) = _s;                                                       \
        (lo) = __fadd_rn((lo), _e);                                      \
    }

static __device__ __forceinline__ unsigned short hbits(__half h) {
    return *reinterpret_cast<unsigned short*>(&h);
}

// split fp32 into 2 fp16 bit patterns (RN)
static __device__ __forceinline__ void split2h(float v, unsigned short& u1,
                                               unsigned short& u2) {
    const __half s1 = __float2half_rn(v);
    const float r1 = __fsub_rn(v, __half2float(s1));
    const __half s2 = __float2half_rn(r1);
    u1 = hbits(s1); u2 = hbits(s2);
}

// mma.sync m16n8k16 fp16 -> fp32, C += A*B
static __device__ __forceinline__ void mma16816h(float* c, const uint32_t* a,
                                                 const uint32_t* b) {
    asm volatile(
        "mma.sync.aligned.m16n8k16.row.col.f32.f16.f16.f32 "
        "{%0,%1,%2,%3}, {%4,%5,%6,%7}, {%8,%9}, {%0,%1,%2,%3};"
        : "+f"(c[0]), "+f"(c[1]), "+f"(c[2]), "+f"(c[3])
        : "r"(a[0]), "r"(a[1]), "r"(a[2]), "r"(a[3]), "r"(b[0]), "r"(b[1]));
}

static __device__ __forceinline__ uint32_t smem_u32(const void* p) {
    uint32_t a;
    asm("{ .reg .u64 t; cvta.to.shared.u64 t, %1; cvt.u32.u64 %0, t; }" : "=r"(a) : "l"(p));
    return a;
}

// ---------------- 0a: weight split (scaled by 2^12) into fragment layout ------
// Thread per (ot, st, oct, kstep, lane). Each writes 2 uint4 (one per split).
__global__ void k_prep_wfrag(const float* __restrict__ w) {
    const int i = blockIdx.x * blockDim.x + threadIdx.x;
    const int NTOT = 4 * NST * 8 * 2 * 32;
    if (i >= NTOT) return;
    const int lane  = i & 31;
    const int kstep = (i >> 5) & 1;
    const int oct   = (i >> 6) & 7;
    const int st    = (i >> 9) % NST;
    const int ot    = i / (NST << 9);
    const int tap = st >> 5;
    const int icb = (st & 31) << 5;

    uint32_t regs[2][4];
#pragma unroll
    for (int s = 0; s < 2; s++)
#pragma unroll
        for (int r = 0; r < 4; r++) regs[s][r] = 0u;

#pragma unroll
    for (int r = 0; r < 4; r++) {
#pragma unroll
        for (int h = 0; h < 2; h++) {
            const int m  = (lane >> 2) + 8 * (r & 1);
            const int kk = 2 * (lane & 3) + h + 8 * (r >> 1);
            const int oc = ot * 128 + oct * 16 + m;
            const int ic = icb + kstep * 16 + kk;
            // scale by 2^12 (exact): residual split stays in fp16 normal range
            const float v = w[((size_t)oc * DIN + ic) * 9 + tap] * WSCALE;
            unsigned short u1, u2;
            split2h(v, u1, u2);
            regs[0][r] |= (uint32_t)u1 << (16 * h);
            regs[1][r] |= (uint32_t)u2 << (16 * h);
        }
    }
    const int fidx = (oct * 2 + kstep) * 32 + lane;   // 0..511
#pragma unroll
    for (int s = 0; s < 2; s++) {
        const size_t b32 = (((size_t)(ot * NST + st) * 2 + s) * 2048) + (size_t)fidx * 4;
        reinterpret_cast<uint4*>(g_wfrag)[b32 >> 2] =
            make_uint4(regs[s][0], regs[s][1], regs[s][2], regs[s][3]);
    }
}

// ---------------- 0b: pack heads weights [c][o] -------------------------------
__global__ void k_prep_headw(const float* __restrict__ cls_w,
                             const float* __restrict__ bbox_w) {
    int i = blockIdx.x * blockDim.x + threadIdx.x;
    if (i >= DIN * 64) return;
    const int o = i & 63;
    const int c = i >> 6;
    float v = 0.f;
    if (c < CHN) {
        if (o < 18)      v = cls_w[(size_t)o * CHN + c];
        else if (o < 54) v = bbox_w[(size_t)(o - 18) * CHN + c];
    }
    g_wpad[i] = v;
}

// ---------------- 1: 3x3 conv via mma.sync fp16 double-split (scaled) ---------
// 512 threads, 16 warps: warp = (oc-group of 16) x (sp-half of 32).
// 4 mmas per k16: s1s1, s1s2, s2s1, s2s2. Result unscaled by 2^-12 at epilogue.
// A tiles via cp.async; fold into hi/lo every 2 stages (K=64).
__global__ __launch_bounds__(512, 1) void k_conv_mma(
    const float* __restrict__ in, const float* __restrict__ bias) {
    extern __shared__ char smem[];
    const uint32_t smem_base = smem_u32(smem);
    const int tid  = threadIdx.x;
    const int wrp  = tid >> 5;
    const int lane = tid & 31;

    const int ot  = blockIdx.y;
    const int b   = blockIdx.z;
    const int sp0 = blockIdx.x * 64;

    const float* inb = in + (size_t)b * DIN * SP;
    const char*  wbase = reinterpret_cast<const char*>(g_wfrag);

    // B producer mapping: 512 threads cover 64 sp x 8 k-quads of 4
    const int bsp = tid & 63;
    const int kq  = tid >> 6;          // 0..7, 4 k each
    const int pos = sp0 + bsp;
    const bool okp = (pos < SP);
    const int ph = pos / WW;
    const int pw = pos - ph * WW;

    float acc[4][4], hi[4][4], lo[4][4];
#pragma unroll
    for (int t2 = 0; t2 < 4; t2++)
#pragma unroll
        for (int r = 0; r < 4; r++) { hi[t2][r] = 0.f; lo[t2][r] = 0.f; }

    float rb[4];

    // issue cp.async for A tile of stage s_ into buffer buf_ (16KB)
#define CONV_A_ASYNC(s_, buf_)                                                 \
    {                                                                          \
        const char* gsrc_ = wbase + ((size_t)(ot * NST + (s_))) * ATILE2;      \
        const uint32_t sdst_ = smem_base + (buf_) * ATILE2;                    \
        _Pragma("unroll")                                                      \
        for (int u = 0; u < 2; u++) {                                          \
            const int off_ = (u * 512 + tid) * 16;                             \
            asm volatile("cp.async.cg.shared.global [%0], [%1], 16;"           \
                :: "r"(sdst_ + off_), "l"(gsrc_ + off_));                      \
        }                                                                      \
        asm volatile("cp.async.commit_group;");                                \
    }

    // prefetch B values of stage s_ into rb
#define CONV_B_PREFETCH(s_)                                                    \
    {                                                                          \
        const int st_ = (s_);                                                  \
        const int tap_ = st_ >> 5;                                             \
        const int ic0_ = (st_ & 31) << 5;                                      \
        const int dy_ = tap_ / 3 - 1, dx_ = tap_ % 3 - 1;                      \
        const int hh_ = ph + dy_, w2_ = pw + dx_;                              \
        const bool ok_ = okp && (hh_ >= 0) && (hh_ < HH) &&                    \
                         (w2_ >= 0) && (w2_ < WW);                             \
        const int ipp_ = hh_ * WW + w2_;                                       \
        _Pragma("unroll")                                                      \
        for (int j = 0; j < 4; j++)                                            \
            rb[j] = ok_ ? __ldg(inb + (size_t)(ic0_ + kq * 4 + j) * SP + ipp_) \
                        : 0.f;                                                 \
    }

    CONV_A_ASYNC(0, 0);
    CONV_B_PREFETCH(0);

    const int oct    = wrp & 7;
    const int spbase = (wrp >> 3) * 32;

    for (int s = 0; s < NST; s++) {
        const int buf = s & 1;
        // ---- store B: split2 + pair-XOR layout (2 pairs per thread)
        {
            char* bbase = smem + SMEM_B_OFF + buf * BTILE2;
#pragma unroll
            for (int j = 0; j < 4; j += 2) {
                const int k  = kq * 4 + j;
                const int pi = k >> 1;
                const int pos2 = (pi & ~3) | ((pi & 3) ^ (bsp & 3));
                unsigned short a1, a2, b1, b2;
                split2h(rb[j],     a1, a2);
                split2h(rb[j + 1], b1, b2);
                char* p = bbase + bsp * BROWB + pos2 * 4;
                *reinterpret_cast<uint32_t*>(p) =
                    (uint32_t)a1 | ((uint32_t)b1 << 16);
                *reinterpret_cast<uint32_t*>(p + BSPLITB) =
                    (uint32_t)a2 | ((uint32_t)b2 << 16);
            }
        }
        // A(s) must have landed before the barrier makes it visible to all
        asm volatile("cp.async.wait_group 0;" ::: "memory");
        __syncthreads();
        if (s + 1 < NST) {
            CONV_A_ASYNC(s + 1, buf ^ 1);
            CONV_B_PREFETCH(s + 1);
        }

        // ---- compute
        const char* abase = smem + buf * ATILE2;
        const char* bbse  = smem + SMEM_B_OFF + buf * BTILE2;
        if ((s & 1) == 0) {
#pragma unroll
            for (int t2 = 0; t2 < 4; t2++)
#pragma unroll
                for (int r = 0; r < 4; r++) acc[t2][r] = 0.f;
        }
#pragma unroll
        for (int kstep = 0; kstep < 2; kstep++) {
            uint32_t af[2][4];
#pragma unroll
            for (int sa = 0; sa < 2; sa++) {
                const uint4 v = *reinterpret_cast<const uint4*>(
                    abase + sa * ASPLIT_B + ((oct * 2 + kstep) * 32 + lane) * 16);
                af[sa][0] = v.x; af[sa][1] = v.y; af[sa][2] = v.z; af[sa][3] = v.w;
            }
#pragma unroll
            for (int spt = 0; spt < 4; spt++) {
                const int spl = spbase + spt * 8 + (lane >> 2);
                const int pbase = kstep * 8 + ((lane & 3) ^ ((lane >> 2) & 3));
                uint32_t bf[2][2];
#pragma unroll
                for (int sb = 0; sb < 2; sb++) {
                    const char* p = bbse + sb * BSPLITB + spl * BROWB + pbase * 4;
                    bf[sb][0] = *reinterpret_cast<const uint32_t*>(p);
                    bf[sb][1] = *reinterpret_cast<const uint32_t*>(p + 16);
                }
                float* C = acc[spt];
                mma16816h(C, af[0], bf[0]);   // s1*s1
                mma16816h(C, af[0], bf[1]);   // s1*s2
                mma16816h(C, af[1], bf[0]);   // s2*s1
                mma16816h(C, af[1], bf[1]);   // s2*s2
            }
        }
        if (s & 1) {
#pragma unroll
            for (int t2 = 0; t2 < 4; t2++)
#pragma unroll
                for (int r = 0; r < 4; r++) {
                    TWOSUM_FOLD(hi[t2][r], lo[t2][r], acc[t2][r]);
                }
        }
    }
#undef CONV_A_ASYNC
#undef CONV_B_PREFETCH

    // ---- epilogue: collapse, unscale by 2^-12 (exact), bias + relu, write g_x
    // C frag: r=0,1 -> row lane>>2, col 2(lane&3)+{0,1}; r=2,3 -> row+8.
#pragma unroll
    for (int spt = 0; spt < 4; spt++) {
#pragma unroll
        for (int r = 0; r < 4; r++) {
            const int oc  = ot * 128 + oct * 16 + (lane >> 2) + 8 * (r >> 1);
            const int spx = sp0 + spbase + spt * 8 + 2 * (lane & 3) + (r & 1);
            if (spx < SP) {
                const float cf = __fmul_rn(__fadd_rn(hi[spt][r], lo[spt][r]),
                                           WSCALE_INV);
                const float v  = __fadd_rn(cf, bias[oc]);
                g_x[((size_t)b * CHN + oc) * SP + spx] = v > 0.f ? v : 0.f;
            }
        }
    }
}

// ---------------- 2: 1x1 heads as 64x64-tile GEMM -----------------------------
#define ZERO44(c)                                       \
    {                                                   \
        _Pragma("unroll")                               \
        for (int _i = 0; _i < 4; _i++)                  \
            _Pragma("unroll")                           \
            for (int _j = 0; _j < 4; _j++) c[_i][_j] = 0.f; \
    }
#define ADD44(a, c)                                     \
    {                                                   \
        _Pragma("unroll")                               \
        for (int _i = 0; _i < 4; _i++)                  \
            _Pragma("unroll")                           \
            for (int _j = 0; _j < 4; _j++)              \
                a[_i][_j] = __fadd_rn(a[_i][_j], c[_i][_j]); \
    }
#define ACC8(c, As, Bs, kb_)                                                   \
    {                                                                          \
        _Pragma("unroll")                                                      \
        for (int kk2 = 0; kk2 < 8; kk2++) {                                    \
            const int kk = (kb_) + kk2;                                        \
            const float4 av = *reinterpret_cast<const float4*>(&(As)[kk][ty*4]);\
            const float4 bv = *reinterpret_cast<const float4*>(&(Bs)[kk][tx*4]);\
            c[0][0] = fmaf(av.x, bv.x, c[0][0]); c[0][1] = fmaf(av.x, bv.y, c[0][1]); \
            c[0][2] = fmaf(av.x, bv.z, c[0][2]); c[0][3] = fmaf(av.x, bv.w, c[0][3]); \
            c[1][0] = fmaf(av.y, bv.x, c[1][0]); c[1][1] = fmaf(av.y, bv.y, c[1][1]); \
            c[1][2] = fmaf(av.y, bv.z, c[1][2]); c[1][3] = fmaf(av.y, bv.w, c[1][3]); \
            c[2][0] = fmaf(av.z, bv.x, c[2][0]); c[2][1] = fmaf(av.z, bv.y, c[2][1]); \
            c[2][2] = fmaf(av.z, bv.z, c[2][2]); c[2][3] = fmaf(av.z, bv.w, c[2][3]); \
            c[3][0] = fmaf(av.w, bv.x, c[3][0]); c[3][1] = fmaf(av.w, bv.y, c[3][1]); \
            c[3][2] = fmaf(av.w, bv.z, c[3][2]); c[3][3] = fmaf(av.w, bv.w, c[3][3]); \
        }                                                                      \
    }

__global__ __launch_bounds__(256, 2) void k_heads_gemm(
    const float* __restrict__ cls_b, const float* __restrict__ bbox_b) {
    const int b   = blockIdx.z;
    const int sp0 = blockIdx.x * 64;
    const int t   = threadIdx.x;
    const int tx  = t & 15;
    const int ty  = t >> 4;

    __shared__ float a_s[2][32][64];
    __shared__ float b_s[2][32][64];

    float hi[4][4], lo[4][4], cA[4][4];
#pragma unroll
    for (int i = 0; i < 4; i++)
#pragma unroll
        for (int j = 0; j < 4; j++) { hi[i][j] = 0.f; lo[i][j] = 0.f; }

    const float* xb = g_x + (size_t)b * CHN * SP;

    const int ss  = t & 63;
    const int pos = sp0 + ss;
    const bool okp = (pos < SP);
    const int kb  = t >> 6;

    const int a_kk = t >> 4;
    const int a_oo = (t & 15) * 4;

    float4 ra0, ra1;
    float rb[8];

#define HEAD_PREFETCH(s_)                                                      \
    {                                                                          \
        const int ic0_ = (s_) << 5;                                            \
        const float* wt_ = g_wpad + (size_t)(ic0_ + a_kk) * 64 + a_oo;         \
        ra0 = *reinterpret_cast<const float4*>(wt_);                           \
        ra1 = *reinterpret_cast<const float4*>(wt_ + 16 * 64);                 \
        _Pragma("unroll")                                                      \
        for (int u = 0; u < 8; u++) {                                          \
            rb[u] = okp ? xb[(size_t)(ic0_ + kb + u * 4) * SP + pos] : 0.f;    \
        }                                                                      \
    }

    HEAD_PREFETCH(0);

    for (int s = 0; s < NSTAGE_HEAD; s++) {
        const int buf = s & 1;
        *reinterpret_cast<float4*>(&a_s[buf][a_kk][a_oo])      = ra0;
        *reinterpret_cast<float4*>(&a_s[buf][a_kk + 16][a_oo]) = ra1;
#pragma unroll
        for (int u = 0; u < 8; u++) b_s[buf][kb + u * 4][ss] = rb[u];
        __syncthreads();
        if (s + 1 < NSTAGE_HEAD) HEAD_PREFETCH(s + 1);
        float cB[4][4];
        if ((s & 1) == 0) {
            ZERO44(cA);
            ACC8(cA, a_s[buf], b_s[buf], 0);
        } else {
            ZERO44(cB);
            ACC8(cB, a_s[buf], b_s[buf], 0);
            ADD44(cA, cB);
        }
#pragma unroll
        for (int u = 1; u < 4; u++) {
            ZERO44(cB);
            ACC8(cB, a_s[buf], b_s[buf], 8 * u);
            ADD44(cA, cB);
        }
        if (s & 1) {
#pragma unroll
            for (int i = 0; i < 4; i++)
#pragma unroll
                for (int j = 0; j < 4; j++) {
                    TWOSUM_FOLD(hi[i][j], lo[i][j], cA[i][j]);
                }
        }
    }
#undef HEAD_PREFETCH

#pragma unroll
    for (int i = 0; i < 4; i++) {
        const int o = ty * 4 + i;
        if (o >= 54) continue;
        const float bv = (o < 18) ? cls_b[o] : bbox_b[o - 18];
        float* outp = (o < 18)
            ? (g_cls  + ((size_t)b * 18 + o)        * SP)
            : (g_bbox + ((size_t)b * 36 + (o - 18)) * SP);
#pragma unroll
        for (int j = 0; j < 4; j++) {
            const int p = sp0 + tx * 4 + j;
            if (p < SP) {
                const float cf = __fadd_rn(hi[i][j], lo[i][j]);
                outp[p] = __fadd_rn(cf, bv);
            }
        }
    }
}

// ---------------- 3: decode + clip + filter + key build ----------------------
__device__ __forceinline__ unsigned int fmono(float f) {
    unsigned int u = __float_as_uint(f);
    return (u & 0x80000000u) ? ~u : (u | 0x80000000u);
}
__device__ __forceinline__ float fmono_inv(unsigned int u) {
    unsigned int v = (u & 0x80000000u) ? (u & 0x7FFFFFFFu) : ~u;
    return __uint_as_float(v);
}

__global__ void k_decode(const float* __restrict__ im_info) {
    const int i = blockIdx.x * blockDim.x + threadIdx.x;
    const int b = blockIdx.y;
    if (i >= NPAD) return;
    if (i >= KTOT) { g_keys[(size_t)b * NPAD + i] = 0ull; return; }

    const int pos = i / AN;
    const int a   = i - pos * AN;
    const int h   = pos / WW;
    const int w   = pos - h * WW;

    const float c0 = g_cls[((size_t)b * 18 + a) * SP + pos];
    const float c1 = g_cls[((size_t)b * 18 + 9 + a) * SP + pos];
    const float m  = fmaxf(c0, c1);
    const float e0 = expf(__fsub_rn(c0, m));
    const float e1 = expf(__fsub_rn(c1, m));
    const float fg = e1 / __fadd_rn(e0, e1);

    const float d0 = g_bbox[((size_t)b * 36 + a * 4 + 0) * SP + pos];
    const float d1 = g_bbox[((size_t)b * 36 + a * 4 + 1) * SP + pos];
    const float d2 = g_bbox[((size_t)b * 36 + a * 4 + 2) * SP + pos];
    const float d3 = g_bbox[((size_t)b * 36 + a * 4 + 3) * SP + pos];

    const float sx = w * STRIDE_F, sy = h * STRIDE_F;
    const float ax1 = __fadd_rn(c_ab[a][0], sx), ay1 = __fadd_rn(c_ab[a][1], sy);
    const float ax2 = __fadd_rn(c_ab[a][2], sx), ay2 = __fadd_rn(c_ab[a][3], sy);
    const float aw  = __fadd_rn(__fsub_rn(ax2, ax1), 1.f);
    const float ah  = __fadd_rn(__fsub_rn(ay2, ay1), 1.f);
    const float axc = __fadd_rn(ax1, __fmul_rn(0.5f, aw));
    const float ayc = __fadd_rn(ay1, __fmul_rn(0.5f, ah));

    const float cx  = __fadd_rn(axc, __fmul_rn(d0, aw));
    const float cy  = __fadd_rn(ayc, __fmul_rn(d1, ah));
    const float pw  = __fmul_rn(expf(d2), aw);
    const float phh = __fmul_rn(expf(d3), ah);

    float x1 = __fsub_rn(cx, __fmul_rn(0.5f, pw));
    float y1 = __fsub_rn(cy, __fmul_rn(0.5f, phh));
    float x2 = __fadd_rn(cx, __fmul_rn(0.5f, pw));
    float y2 = __fadd_rn(cy, __fmul_rn(0.5f, phh));

    const float i0 = im_info[b * 3 + 0];
    const float i1 = im_info[b * 3 + 1];
    const float i2 = im_info[b * 3 + 2];
    x1 = fminf(fmaxf(x1, 0.f), __fsub_rn(i1, 1.f));
    x2 = fminf(fmaxf(x2, 0.f), __fsub_rn(i1, 1.f));
    y1 = fminf(fmaxf(y1, 0.f), __fsub_rn(i0, 1.f));
    y2 = fminf(fmaxf(y2, 0.f), __fsub_rn(i0, 1.f));

    const float ws = __fadd_rn(__fsub_rn(x2, x1), 1.f);
    const float hs = __fadd_rn(__fsub_rn(y2, y1), 1.f);
    const float ms = __fmul_rn(MIN_SIZE, i2);
    const float score = (ws >= ms && hs >= ms) ? fg : -INFINITY;

    float* bo = g_boxes + ((size_t)b * KTOT + i) * 4;
    bo[0] = x1; bo[1] = y1; bo[2] = x2; bo[3] = y2;

    g_keys[(size_t)b * NPAD + i] =
        ((ull)fmono(score) << 32) | (ull)(0xFFFFFFFFu - (unsigned)i);
}

// ---------------- 4a: sort 8192-chunks descending in smem ---------------------
__global__ __launch_bounds__(1024) void k_sort_chunk() {
    extern __shared__ ull sh[];
    const int b = blockIdx.y;
    ull* g = g_keys + (size_t)b * NPAD + (size_t)blockIdx.x * CHUNK;
    for (int i = threadIdx.x; i < CHUNK; i += 1024) sh[i] = g[i];
    __syncthreads();
    for (int len = 2; len <= CHUNK; len <<= 1) {
        for (int j = len >> 1; j > 0; j >>= 1) {
            for (int i = threadIdx.x; i < CHUNK; i += 1024) {
                const int ixj = i ^ j;
                if (ixj > i) {
                    const ull a = sh[i], c = sh[ixj];
                    const bool desc = ((i & len) == 0);
                    if (desc ? (a < c) : (a > c)) { sh[i] = c; sh[ixj] = a; }
                }
            }
            __syncthreads();
        }
    }
    for (int i = threadIdx.x; i < CHUNK; i += 1024) g[i] = sh[i];
}

// ---------------- 4b: merge two sorted-desc runs, keep top CHUNK --------------
__global__ __launch_bounds__(1024) void k_merge_top(int run_stride) {
    extern __shared__ ull sh[];
    const int b = blockIdx.y;
    ull* gA = g_keys + (size_t)b * NPAD + (size_t)blockIdx.x * 2 * run_stride;
    ull* gB = gA + run_stride;
    for (int i = threadIdx.x; i < CHUNK; i += 1024) {
        const ull a = gA[i];
        const ull c = gB[CHUNK - 1 - i];
        sh[i] = a > c ? a : c;
    }
    __syncthreads();
    for (int j = CHUNK >> 1; j > 0; j >>= 1) {
        for (int i = threadIdx.x; i < CHUNK; i += 1024) {
            const int ixj = i ^ j;
            if (ixj > i) {
                const ull a = sh[i], c = sh[ixj];
                if (a < c) { sh[i] = c; sh[ixj] = a; }
            }
        }
        __syncthreads();
    }
    for (int i = threadIdx.x; i < CHUNK; i += 1024) gA[i] = sh[i];
}

// ---------------- 5: gather top-k --------------------------------------------
__global__ void k_gather() {
    const int i = blockIdx.x * blockDim.x + threadIdx.x;
    const int b = blockIdx.y;
    if (i >= PRE_NMS) return;
    const ull key = g_keys[(size_t)b * NPAD + i];
    const unsigned int idx = 0xFFFFFFFFu - (unsigned int)(key & 0xFFFFFFFFull);
    g_ts[(size_t)b * PRE_NMS + i] = fmono_inv((unsigned int)(key >> 32));
    const float* src = g_boxes + ((size_t)b * KTOT + idx) * 4;
    float* dst = g_tb + ((size_t)b * PRE_NMS + i) * 4;
    dst[0] = src[0]; dst[1] = src[1]; dst[2] = src[2]; dst[3] = src[3];
}

// ---------------- 6: greedy NMS, 1 block per image ---------------------------
__global__ __launch_bounds__(1024) void k_nms() {
    const int b = blockIdx.x;
    const int tid = threadIdx.x;
    __shared__ unsigned char alive[PRE_NMS];
    __shared__ int s_head, s_cur;

    const float* ts = g_ts + (size_t)b * PRE_NMS;
    const float* tb = g_tb + (size_t)b * PRE_NMS * 4;

    for (int i = tid; i < PRE_NMS; i += blockDim.x)
        alive[i] = (ts[i] != -INFINITY) ? 1 : 0;
    if (tid == 0) s_head = 0;
    __syncthreads();

    for (int r = 0; r < POST_NMS; r++) {
        if (tid == 0) {
            int h = s_head;
            while (h < PRE_NMS && !alive[h]) h++;
            s_head = h;
            s_cur = (h < PRE_NMS) ? h : 0;
            g_keep[b * POST_NMS + r] = s_cur;
        }
        __syncthreads();
        const int j = s_cur;
        const float jx1 = tb[j * 4 + 0], jy1 = tb[j * 4 + 1];
        const float jx2 = tb[j * 4 + 2], jy2 = tb[j * 4 + 3];
        const float ja = __fmul_rn(__fadd_rn(__fsub_rn(jx2, jx1), 1.f),
                                   __fadd_rn(__fsub_rn(jy2, jy1), 1.f));
        for (int i = tid; i < PRE_NMS; i += blockDim.x) {
            if (!alive[i]) continue;
            const float x1 = tb[i * 4 + 0], y1 = tb[i * 4 + 1];
            const float x2 = tb[i * 4 + 2], y2 = tb[i * 4 + 3];
            const float xx1 = fmaxf(jx1, x1), yy1 = fmaxf(jy1, y1);
            const float xx2 = fminf(jx2, x2), yy2 = fminf(jy2, y2);
            const float iw = fmaxf(0.f, __fadd_rn(__fsub_rn(xx2, xx1), 1.f));
            const float ih = fmaxf(0.f, __fadd_rn(__fsub_rn(yy2, yy1), 1.f));
            const float inter = __fmul_rn(iw, ih);
            const float ia = __fmul_rn(__fadd_rn(__fsub_rn(x2, x1), 1.f),
                                       __fadd_rn(__fsub_rn(y2, y1), 1.f));
            const float iou = inter / __fsub_rn(__fadd_rn(ja, ia), inter);
            if (iou > NMS_THRESH) alive[i] = 0;
        }
        __syncthreads();
    }
}

// ---------------- 7: write outputs -------------------------------------------
__global__ void k_writeout(float* __restrict__ out) {
    const int t = blockIdx.x * blockDim.x + threadIdx.x;
    if (t >= BB * POST_NMS) return;
    const int b = t / POST_NMS;
    const int j = g_keep[t];
    out[t] = g_ts[(size_t)b * PRE_NMS + j];
    const float* src = g_tb + ((size_t)b * PRE_NMS + j) * 4;
    float* dst = out + BB * POST_NMS + (size_t)t * 4;
    dst[0] = src[0]; dst[1] = src[1]; dst[2] = src[2]; dst[3] = src[3];
}

// ---------------- launch ------------------------------------------------------
extern "C" void kernel_launch(void* const* d_in, const int* in_sizes, int n_in,
                              void* d_out, int out_size) {
    const float* base_feat = (const float*)d_in[0];
    const float* im_info   = (const float*)d_in[1];
    // d_in[2] gt_boxes, d_in[3] num_boxes: unused
    const float* conv_w    = (const float*)d_in[4];
    const float* conv_b    = (const float*)d_in[5];
    const float* cls_w     = (const float*)d_in[6];
    const float* cls_b     = (const float*)d_in[7];
    const float* bbox_w    = (const float*)d_in[8];
    const float* bbox_b    = (const float*)d_in[9];
    float* out = (float*)d_out;

    const int SORT_SMEM = CHUNK * (int)sizeof(ull);   // 64KB
    cudaFuncSetAttribute(k_sort_chunk, cudaFuncAttributeMaxDynamicSharedMemorySize, SORT_SMEM);
    cudaFuncSetAttribute(k_merge_top,  cudaFuncAttributeMaxDynamicSharedMemorySize, SORT_SMEM);
    cudaFuncSetAttribute(k_conv_mma,   cudaFuncAttributeMaxDynamicSharedMemorySize, SMEM_CONV_TOTAL);

    {   // weight prep: fragment-layout fp16 double-split (2^12-scaled); heads pack
        const int n = 4 * NST * 8 * 2 * 32;
        k_prep_wfrag<<<(n + 255) / 256, 256>>>(conv_w);
        k_prep_headw<<<(DIN * 64 + 255) / 256, 256>>>(cls_w, bbox_w);
    }
    {   // conv via mma.sync fp16 (4 mmas per k16), 512 threads / 16 warps
        dim3 grid((SP + 63) / 64, 4, BB);
        k_conv_mma<<<grid, 512, SMEM_CONV_TOTAL>>>(base_feat, conv_b);
    }
    {   // heads GEMM
        dim3 grid((SP + 63) / 64, 1, BB);
        k_heads_gemm<<<grid, 256>>>(cls_b, bbox_b);
    }
    {   // decode
        dim3 grid((NPAD + 255) / 256, BB);
        k_decode<<<grid, 256>>>(im_info);
    }
    {   // sort: 8 chunk-sorts, then top-8192 merge tree 8 -> 4 -> 2 -> 1
        dim3 g0(NPAD / CHUNK, BB);
        k_sort_chunk<<<g0, 1024, SORT_SMEM>>>();
        dim3 g1(4, BB); k_merge_top<<<g1, 1024, SORT_SMEM>>>(CHUNK);
        dim3 g2(2, BB); k_merge_top<<<g2, 1024, SORT_SMEM>>>(2 * CHUNK);
        dim3 g3(1, BB); k_merge_top<<<g3, 1024, SORT_SMEM>>>(4 * CHUNK);
    }
    {
        dim3 grid((PRE_NMS + 255) / 256, BB);
        k_gather<<<grid, 256>>>();
    }
    k_nms<<<BB, 1024>>>();
    k_writeout<<<(BB * POST_NMS + 255) / 256, 256>>>(out);
}